// round 4
// baseline (speedup 1.0000x reference)
#include <cuda_runtime.h>
#include <cuda_bf16.h>

#define T_DIM 8192

__device__ float        g_scratch = 0.0f;
__device__ unsigned int g_count   = 0u;

__global__ void __launch_bounds__(256, 4)
wl_reduce(const float4* __restrict__ a, const float4* __restrict__ b,
          float* __restrict__ out, int n4, float scale) {
    const int stride = gridDim.x * blockDim.x;
    float acc = 0.0f;

    for (int i = blockIdx.x * blockDim.x + threadIdx.x; i < n4; i += stride) {
        float4 va = a[i];
        float4 vb = b[i];
        float w = (float)(T_DIM - ((i << 2) & (T_DIM - 1)));
        acc = fmaf(fabsf(va.x - vb.x), w,        acc);
        acc = fmaf(fabsf(va.y - vb.y), w - 1.0f, acc);
        acc = fmaf(fabsf(va.z - vb.z), w - 2.0f, acc);
        acc = fmaf(fabsf(va.w - vb.w), w - 3.0f, acc);
    }

    // intra-warp reduce
    #pragma unroll
    for (int o = 16; o > 0; o >>= 1)
        acc += __shfl_down_sync(0xffffffffu, acc, o);

    __shared__ float smem[8];
    const int lane = threadIdx.x & 31;
    const int wid  = threadIdx.x >> 5;
    if (lane == 0) smem[wid] = acc;
    __syncthreads();
    if (wid == 0) {
        acc = (lane < 8) ? smem[lane] : 0.0f;
        #pragma unroll
        for (int o = 4; o > 0; o >>= 1)
            acc += __shfl_down_sync(0xffffffffu, acc, o);

        if (lane == 0) {
            atomicAdd(&g_scratch, acc);
            __threadfence();
            unsigned int old = atomicAdd(&g_count, 1u);
            if (old == gridDim.x - 1) {
                out[0]    = g_scratch * scale;
                g_scratch = 0.0f;
                g_count   = 0u;
            }
        }
    }
}

extern "C" void kernel_launch(void* const* d_in, const int* in_sizes, int n_in,
                              void* d_out, int out_size) {
    const float4* y_pred = (const float4*)d_in[0];
    const float4* y_true = (const float4*)d_in[1];
    float* out = (float*)d_out;

    const int n  = in_sizes[0];   // 32*64*8192
    const int n4 = n / 4;

    const double T = (double)T_DIM;
    const double C = 64.0;
    const double B = (double)n / (T * C);
    const float scale = (float)(2.0 / (T * C * (T + 1.0) * B));

    // One balanced resident wave: 148 SMs x 4 CTAs (256 thr, ~26 regs).
    const int threads = 256;
    int blocks = 148 * 4;
    int max_blocks = (n4 + threads - 1) / threads;
    if (blocks > max_blocks) blocks = max_blocks;

    wl_reduce<<<blocks, threads>>>(y_pred, y_true, out, n4, scale);
}

// round 5
// speedup vs baseline: 1.1837x; 1.1837x over previous
#include <cuda_runtime.h>
#include <cuda_bf16.h>

#define T_DIM 8192

__device__ float        g_scratch = 0.0f;
__device__ unsigned int g_count   = 0u;

__global__ void __launch_bounds__(256, 8)
wl_reduce(const float4* __restrict__ a, const float4* __restrict__ b,
          float* __restrict__ out, int n4, float scale) {
    const int stride = gridDim.x * blockDim.x;
    float acc = 0.0f;

    for (int i = blockIdx.x * blockDim.x + threadIdx.x; i < n4; i += stride) {
        float4 va = a[i];
        float4 vb = b[i];
        float w = (float)(T_DIM - ((i << 2) & (T_DIM - 1)));
        acc = fmaf(fabsf(va.x - vb.x), w,        acc);
        acc = fmaf(fabsf(va.y - vb.y), w - 1.0f, acc);
        acc = fmaf(fabsf(va.z - vb.z), w - 2.0f, acc);
        acc = fmaf(fabsf(va.w - vb.w), w - 3.0f, acc);
    }

    // intra-warp reduce
    #pragma unroll
    for (int o = 16; o > 0; o >>= 1)
        acc += __shfl_down_sync(0xffffffffu, acc, o);

    __shared__ float smem[8];
    const int lane = threadIdx.x & 31;
    const int wid  = threadIdx.x >> 5;
    if (lane == 0) smem[wid] = acc;
    __syncthreads();
    if (wid == 0) {
        acc = (lane < 8) ? smem[lane] : 0.0f;
        #pragma unroll
        for (int o = 4; o > 0; o >>= 1)
            acc += __shfl_down_sync(0xffffffffu, acc, o);

        if (lane == 0) {
            atomicAdd(&g_scratch, acc);
            __threadfence();
            unsigned int old = atomicAdd(&g_count, 1u);
            if (old == gridDim.x - 1) {
                out[0]    = g_scratch * scale;
                g_scratch = 0.0f;
                g_count   = 0u;
            }
        }
    }
}

extern "C" void kernel_launch(void* const* d_in, const int* in_sizes, int n_in,
                              void* d_out, int out_size) {
    const float4* y_pred = (const float4*)d_in[0];
    const float4* y_true = (const float4*)d_in[1];
    float* out = (float*)d_out;

    const int n  = in_sizes[0];   // 32*64*8192
    const int n4 = n / 4;

    const double T = (double)T_DIM;
    const double C = 64.0;
    const double B = (double)n / (T * C);
    const float scale = (float)(2.0 / (T * C * (T + 1.0) * B));

    // One full resident wave: 148 SMs x 8 CTAs x 256 thr = 64 warps/SM.
    const int threads = 256;
    int blocks = 148 * 8;
    int max_blocks = (n4 + threads - 1) / threads;
    if (blocks > max_blocks) blocks = max_blocks;

    wl_reduce<<<blocks, threads>>>(y_pred, y_true, out, n4, scale);
}